// round 1
// baseline (speedup 1.0000x reference)
#include <cuda_runtime.h>

#define NBINS 15
#define BS 256
#define NACC (2 + NBINS)
#define GRID 1216

// [0]=focal sum, [1]=cp sum, [2..16]=per-bin sum of (y - p)
__device__ double g_acc[NACC];

__global__ void fcl_init() {
    if (threadIdx.x < NACC) g_acc[threadIdx.x] = 0.0;
}

__device__ __forceinline__ float warp_sum(float v) {
#pragma unroll
    for (int o = 16; o > 0; o >>= 1) v += __shfl_down_sync(0xffffffffu, v, o);
    return v;
}

__global__ void __launch_bounds__(BS) fcl_main(
    const float* __restrict__ p_hat, const float* __restrict__ u_hat,
    const int* __restrict__ targets, int n)
{
    __shared__ float hist[NBINS * BS];   // hist[b*BS + tid] -> bank = tid%32, conflict-free
    __shared__ float red[2][BS / 32];

    const int tid  = threadIdx.x;
    const int lane = tid & 31;
    const int warp = tid >> 5;

#pragma unroll
    for (int b = 0; b < NBINS; b++) hist[b * BS + tid] = 0.0f;
    __syncthreads();

    float facc = 0.0f, cacc = 0.0f;

    const int n4 = n >> 2;
    const float4* __restrict__ p4 = (const float4*)p_hat;
    const float4* __restrict__ u4 = (const float4*)u_hat;
    const int4*   __restrict__ t4 = (const int4*)targets;

    const int stride = gridDim.x * BS;
    for (int i = blockIdx.x * BS + tid; i < n4; i += stride) {
        float4 pv = p4[i];
        float4 uv = u4[i];
        int4   tv = t4[i];
        float pr[4] = {pv.x, pv.y, pv.z, pv.w};
        float ur[4] = {uv.x, uv.y, uv.z, uv.w};
        int   tr[4] = {tv.x, tv.y, tv.z, tv.w};
#pragma unroll
        for (int k = 0; k < 4; k++) {
            float p = pr[k];
            float u = ur[k];
            bool pos = (tr[k] == 1);

            // focal: -alpha * (1-pt)^2 * log(pt + 1e-12)
            float pt = pos ? p : 1.0f - p;
            float al = pos ? 1.0f : 2.0f;
            float om = 1.0f - pt;
            facc -= al * om * om * __logf(pt + 1e-12f);

            // confidence penalty
            float pen = 0.0f;
            if (pos) {
                if (p < 0.7f) pen = u * u;
            } else {
                if (p > 0.7f) { float w = 1.0f - u; pen = w * w; }
            }
            cacc += pen;

            // ECE binning: b = clip(ceil(p*15)-1, 0, 14); accumulate (y - p)
            int b = (int)ceilf(p * 15.0f) - 1;
            b = b < 0 ? 0 : (b > NBINS - 1 ? NBINS - 1 : b);
            float d = (pos ? 1.0f : 0.0f) - p;
            hist[b * BS + tid] += d;
        }
    }

    // scalar tail (n not divisible by 4)
    for (int i = (n4 << 2) + blockIdx.x * BS + tid; i < n; i += stride) {
        float p = p_hat[i];
        float u = u_hat[i];
        bool pos = (targets[i] == 1);
        float pt = pos ? p : 1.0f - p;
        float al = pos ? 1.0f : 2.0f;
        float om = 1.0f - pt;
        facc -= al * om * om * __logf(pt + 1e-12f);
        float pen = 0.0f;
        if (pos) { if (p < 0.7f) pen = u * u; }
        else     { if (p > 0.7f) { float w = 1.0f - u; pen = w * w; } }
        cacc += pen;
        int b = (int)ceilf(p * 15.0f) - 1;
        b = b < 0 ? 0 : (b > NBINS - 1 ? NBINS - 1 : b);
        hist[b * BS + tid] += (pos ? 1.0f : 0.0f) - p;
    }
    __syncthreads();

    // block-reduce focal / cp
    facc = warp_sum(facc);
    cacc = warp_sum(cacc);
    if (lane == 0) { red[0][warp] = facc; red[1][warp] = cacc; }
    __syncthreads();
    if (warp == 0) {
        float f = (lane < BS / 32) ? red[0][lane] : 0.0f;
        float c = (lane < BS / 32) ? red[1][lane] : 0.0f;
        f = warp_sum(f);
        c = warp_sum(c);
        if (lane == 0) {
            atomicAdd(&g_acc[0], (double)f);
            atomicAdd(&g_acc[1], (double)c);
        }
    }

    // block-reduce each bin column, one double atomic per bin per block
    for (int b = warp; b < NBINS; b += BS / 32) {
        float s = 0.0f;
#pragma unroll
        for (int j = lane; j < BS; j += 32) s += hist[b * BS + j];
        s = warp_sum(s);
        if (lane == 0) atomicAdd(&g_acc[2 + b], (double)s);
    }
}

__global__ void fcl_fin(float* __restrict__ out, int n) {
    if (threadIdx.x == 0) {
        double invn  = 1.0 / (double)n;
        double focal = g_acc[0] * invn;
        double cp    = g_acc[1] * invn;
        double e     = 0.0;
#pragma unroll
        for (int b = 0; b < NBINS; b++) e += fabs(g_acc[2 + b]);
        e *= invn;
        out[0] = (float)(focal + 6.0 * cp + 5.0 * e);
    }
}

extern "C" void kernel_launch(void* const* d_in, const int* in_sizes, int n_in,
                              void* d_out, int out_size) {
    const float* p_hat   = (const float*)d_in[0];
    const float* u_hat   = (const float*)d_in[1];
    const int*   targets = (const int*)d_in[2];
    float* out = (float*)d_out;
    int n = in_sizes[0];

    fcl_init<<<1, 32>>>();
    fcl_main<<<GRID, BS>>>(p_hat, u_hat, targets, n);
    fcl_fin<<<1, 32>>>(out, n);
}

// round 2
// speedup vs baseline: 1.0108x; 1.0108x over previous
#include <cuda_runtime.h>

#define NBINS 15
#define BS 256
#define NACC (2 + NBINS)
#define GRID 1216

// [0]=focal sum, [1]=cp sum, [2..16]=per-bin sum of (y - p)
__device__ double g_acc[NACC];
__device__ unsigned g_count;   // zero-initialized at module load

__device__ __forceinline__ float warp_sum(float v) {
#pragma unroll
    for (int o = 16; o > 0; o >>= 1) v += __shfl_down_sync(0xffffffffu, v, o);
    return v;
}

__device__ __forceinline__ void process1(float p, float u, int t,
                                         float& facc, float& cacc,
                                         float* __restrict__ histcol) {
    bool pos = (t == 1);

    // focal: -alpha * (1-pt)^2 * log(pt + 1e-12)
    float pt = pos ? p : 1.0f - p;
    float al = pos ? 1.0f : 2.0f;
    float om = 1.0f - pt;
    facc -= al * om * om * __logf(pt + 1e-12f);

    // confidence penalty
    float pen = 0.0f;
    if (pos) {
        if (p < 0.7f) pen = u * u;
    } else {
        if (p > 0.7f) { float w = 1.0f - u; pen = w * w; }
    }
    cacc += pen;

    // ECE binning: b = clip(ceil(p*15)-1, 0, 14); accumulate (y - p)
    int b = (int)ceilf(p * 15.0f) - 1;
    b = b < 0 ? 0 : (b > NBINS - 1 ? NBINS - 1 : b);
    histcol[b * BS] += (pos ? 1.0f : 0.0f) - p;
}

__global__ void __launch_bounds__(BS) fcl_main(
    const float* __restrict__ p_hat, const float* __restrict__ u_hat,
    const int* __restrict__ targets, float* __restrict__ out, int n)
{
    __shared__ float hist[NBINS * BS];   // hist[b*BS + tid] -> bank = tid%32, conflict-free
    __shared__ float red[2][BS / 32];
    __shared__ bool is_last;

    const int tid  = threadIdx.x;
    const int lane = tid & 31;
    const int warp = tid >> 5;
    float* histcol = &hist[tid];

#pragma unroll
    for (int b = 0; b < NBINS; b++) hist[b * BS + tid] = 0.0f;
    __syncthreads();

    float facc = 0.0f, cacc = 0.0f;

    const int n4 = n >> 2;
    const float4* __restrict__ p4 = (const float4*)p_hat;
    const float4* __restrict__ u4 = (const float4*)u_hat;
    const int4*   __restrict__ t4 = (const int4*)targets;

    const int stride = GRID * BS;
    int i = blockIdx.x * BS + tid;

    // unroll-by-2: 6 independent LDG.128 batched up front per iteration
    for (; i + stride < n4; i += 2 * stride) {
        float4 pv0 = __ldcs(&p4[i]);
        float4 uv0 = __ldcs(&u4[i]);
        int4   tv0 = __ldcs(&t4[i]);
        float4 pv1 = __ldcs(&p4[i + stride]);
        float4 uv1 = __ldcs(&u4[i + stride]);
        int4   tv1 = __ldcs(&t4[i + stride]);

        process1(pv0.x, uv0.x, tv0.x, facc, cacc, histcol);
        process1(pv0.y, uv0.y, tv0.y, facc, cacc, histcol);
        process1(pv0.z, uv0.z, tv0.z, facc, cacc, histcol);
        process1(pv0.w, uv0.w, tv0.w, facc, cacc, histcol);
        process1(pv1.x, uv1.x, tv1.x, facc, cacc, histcol);
        process1(pv1.y, uv1.y, tv1.y, facc, cacc, histcol);
        process1(pv1.z, uv1.z, tv1.z, facc, cacc, histcol);
        process1(pv1.w, uv1.w, tv1.w, facc, cacc, histcol);
    }
    for (; i < n4; i += stride) {
        float4 pv = __ldcs(&p4[i]);
        float4 uv = __ldcs(&u4[i]);
        int4   tv = __ldcs(&t4[i]);
        process1(pv.x, uv.x, tv.x, facc, cacc, histcol);
        process1(pv.y, uv.y, tv.y, facc, cacc, histcol);
        process1(pv.z, uv.z, tv.z, facc, cacc, histcol);
        process1(pv.w, uv.w, tv.w, facc, cacc, histcol);
    }
    // scalar tail (n not divisible by 4)
    for (int j = (n4 << 2) + blockIdx.x * BS + tid; j < n; j += stride) {
        process1(p_hat[j], u_hat[j], targets[j], facc, cacc, histcol);
    }
    __syncthreads();

    // block-reduce focal / cp
    facc = warp_sum(facc);
    cacc = warp_sum(cacc);
    if (lane == 0) { red[0][warp] = facc; red[1][warp] = cacc; }
    __syncthreads();
    if (warp == 0) {
        float f = (lane < BS / 32) ? red[0][lane] : 0.0f;
        float c = (lane < BS / 32) ? red[1][lane] : 0.0f;
        f = warp_sum(f);
        c = warp_sum(c);
        if (lane == 0) {
            atomicAdd(&g_acc[0], (double)f);
            atomicAdd(&g_acc[1], (double)c);
        }
    }

    // block-reduce each bin column, one double atomic per bin per block
    for (int b = warp; b < NBINS; b += BS / 32) {
        float s = 0.0f;
#pragma unroll
        for (int j = lane; j < BS; j += 32) s += hist[b * BS + j];
        s = warp_sum(s);
        if (lane == 0) atomicAdd(&g_acc[2 + b], (double)s);
    }

    // last-block-done: finalize + reset accumulators for next graph replay
    __threadfence();
    if (tid == 0) {
        unsigned v = atomicInc(&g_count, GRID - 1);  // wraps to 0 on last block
        is_last = (v == GRID - 1);
    }
    __syncthreads();
    if (is_last && tid == 0) {
        double invn  = 1.0 / (double)n;
        double focal = g_acc[0] * invn;
        double cp    = g_acc[1] * invn;
        double e     = 0.0;
#pragma unroll
        for (int b = 0; b < NBINS; b++) e += fabs(g_acc[2 + b]);
        e *= invn;
        out[0] = (float)(focal + 6.0 * cp + 5.0 * e);
#pragma unroll
        for (int a = 0; a < NACC; a++) g_acc[a] = 0.0;
    }
}

extern "C" void kernel_launch(void* const* d_in, const int* in_sizes, int n_in,
                              void* d_out, int out_size) {
    const float* p_hat   = (const float*)d_in[0];
    const float* u_hat   = (const float*)d_in[1];
    const int*   targets = (const int*)d_in[2];
    float* out = (float*)d_out;
    int n = in_sizes[0];

    fcl_main<<<GRID, BS>>>(p_hat, u_hat, targets, out, n);
}

// round 3
// speedup vs baseline: 1.0167x; 1.0058x over previous
#include <cuda_runtime.h>

#define NBINS 15
#define BS 256
#define NACC (2 + NBINS)
#define GRID 1184   // 148 SMs * 8 blocks

// [0]=focal sum, [1]=cp sum, [2..16]=per-bin sum of (y - p)
__device__ double g_acc[NACC];
__device__ unsigned g_count;   // zero-initialized at module load

__device__ __forceinline__ float warp_sum(float v) {
#pragma unroll
    for (int o = 16; o > 0; o >>= 1) v += __shfl_down_sync(0xffffffffu, v, o);
    return v;
}

__device__ __forceinline__ unsigned long long mkpolicy(float frac) {
    unsigned long long pol;
    asm("createpolicy.fractional.L2::evict_last.L2::evict_first.b64 %0, %1;"
        : "=l"(pol) : "f"(frac));
    return pol;
}

__device__ __forceinline__ float4 ldg_pol_f4(const float4* p, unsigned long long pol) {
    float4 v;
    asm volatile("ld.global.nc.L2::cache_hint.v4.f32 {%0,%1,%2,%3}, [%4], %5;"
                 : "=f"(v.x), "=f"(v.y), "=f"(v.z), "=f"(v.w)
                 : "l"(p), "l"(pol));
    return v;
}

__device__ __forceinline__ int4 ldg_pol_i4(const int4* p, unsigned long long pol) {
    int4 v;
    asm volatile("ld.global.nc.L2::cache_hint.v4.b32 {%0,%1,%2,%3}, [%4], %5;"
                 : "=r"(v.x), "=r"(v.y), "=r"(v.z), "=r"(v.w)
                 : "l"(p), "l"(pol));
    return v;
}

__device__ __forceinline__ void process1(float p, float u, int t,
                                         float& facc, float& cacc,
                                         float* __restrict__ histcol) {
    bool pos = (t != 0);
    float tf = (float)t;

    // focal: -alpha * (1-pt)^2 * log(pt + 1e-12), alpha = 2 - t
    float pt = pos ? p : 1.0f - p;
    float al = 2.0f - tf;
    float om = 1.0f - pt;
    float lg = __logf(pt + 1e-12f);
    facc = fmaf(-al * om * om, lg, facc);

    // confidence penalty: pos&p<tau -> u^2 ; !pos&p>tau -> (1-u)^2
    float v = pos ? u : 1.0f - u;
    bool cond = ((p < 0.7f) == pos);
    float m = v * v;
    if (cond) cacc += m;

    // ECE binning: bin = min((int)(p*15), 14)  (p >= 0)
    int b = (int)(p * 15.0f);
    b = b > NBINS - 1 ? NBINS - 1 : b;
    histcol[b * BS] += tf - p;
}

__global__ void __launch_bounds__(BS) fcl_main(
    const float* __restrict__ p_hat, const float* __restrict__ u_hat,
    const int* __restrict__ targets, float* __restrict__ out, int n)
{
    __shared__ float hist[NBINS * BS];   // hist[b*BS + tid] -> bank = tid%32, conflict-free
    __shared__ float red[2][BS / 32];
    __shared__ bool is_last;

    const int tid  = threadIdx.x;
    const int lane = tid & 31;
    const int warp = tid >> 5;
    float* histcol = &hist[tid];

#pragma unroll
    for (int b = 0; b < NBINS; b++) hist[b * BS + tid] = 0.0f;
    __syncthreads();

    // L2 residency: pin all of p_hat, ~35% of u_hat/targets (addr-hashed, stable)
    const unsigned long long pol_p  = mkpolicy(1.0f);
    const unsigned long long pol_ut = mkpolicy(0.35f);

    float facc = 0.0f, cacc = 0.0f;

    const int n4 = n >> 2;
    const float4* __restrict__ p4 = (const float4*)p_hat;
    const float4* __restrict__ u4 = (const float4*)u_hat;
    const int4*   __restrict__ t4 = (const int4*)targets;

    const int stride = GRID * BS;
    int i = blockIdx.x * BS + tid;

    // unroll-by-2: 6 independent LDG.128 batched up front per iteration
    for (; i + stride < n4; i += 2 * stride) {
        float4 pv0 = ldg_pol_f4(&p4[i], pol_p);
        float4 uv0 = ldg_pol_f4(&u4[i], pol_ut);
        int4   tv0 = ldg_pol_i4(&t4[i], pol_ut);
        float4 pv1 = ldg_pol_f4(&p4[i + stride], pol_p);
        float4 uv1 = ldg_pol_f4(&u4[i + stride], pol_ut);
        int4   tv1 = ldg_pol_i4(&t4[i + stride], pol_ut);

        process1(pv0.x, uv0.x, tv0.x, facc, cacc, histcol);
        process1(pv0.y, uv0.y, tv0.y, facc, cacc, histcol);
        process1(pv0.z, uv0.z, tv0.z, facc, cacc, histcol);
        process1(pv0.w, uv0.w, tv0.w, facc, cacc, histcol);
        process1(pv1.x, uv1.x, tv1.x, facc, cacc, histcol);
        process1(pv1.y, uv1.y, tv1.y, facc, cacc, histcol);
        process1(pv1.z, uv1.z, tv1.z, facc, cacc, histcol);
        process1(pv1.w, uv1.w, tv1.w, facc, cacc, histcol);
    }
    for (; i < n4; i += stride) {
        float4 pv = ldg_pol_f4(&p4[i], pol_p);
        float4 uv = ldg_pol_f4(&u4[i], pol_ut);
        int4   tv = ldg_pol_i4(&t4[i], pol_ut);
        process1(pv.x, uv.x, tv.x, facc, cacc, histcol);
        process1(pv.y, uv.y, tv.y, facc, cacc, histcol);
        process1(pv.z, uv.z, tv.z, facc, cacc, histcol);
        process1(pv.w, uv.w, tv.w, facc, cacc, histcol);
    }
    // scalar tail (n not divisible by 4)
    for (int j = (n4 << 2) + blockIdx.x * BS + tid; j < n; j += stride) {
        process1(p_hat[j], u_hat[j], targets[j], facc, cacc, histcol);
    }
    __syncthreads();

    // block-reduce focal / cp
    facc = warp_sum(facc);
    cacc = warp_sum(cacc);
    if (lane == 0) { red[0][warp] = facc; red[1][warp] = cacc; }
    __syncthreads();
    if (warp == 0) {
        float f = (lane < BS / 32) ? red[0][lane] : 0.0f;
        float c = (lane < BS / 32) ? red[1][lane] : 0.0f;
        f = warp_sum(f);
        c = warp_sum(c);
        if (lane == 0) {
            atomicAdd(&g_acc[0], (double)f);
            atomicAdd(&g_acc[1], (double)c);
        }
    }

    // block-reduce each bin column, one double atomic per bin per block
    for (int b = warp; b < NBINS; b += BS / 32) {
        float s = 0.0f;
#pragma unroll
        for (int j = lane; j < BS; j += 32) s += hist[b * BS + j];
        s = warp_sum(s);
        if (lane == 0) atomicAdd(&g_acc[2 + b], (double)s);
    }

    // last-block-done: finalize + reset accumulators for next graph replay
    __threadfence();
    if (tid == 0) {
        unsigned v = atomicInc(&g_count, GRID - 1);  // wraps to 0 on last block
        is_last = (v == GRID - 1);
    }
    __syncthreads();
    if (is_last && tid == 0) {
        double invn  = 1.0 / (double)n;
        double focal = g_acc[0] * invn;
        double cp    = g_acc[1] * invn;
        double e     = 0.0;
#pragma unroll
        for (int b = 0; b < NBINS; b++) e += fabs(g_acc[2 + b]);
        e *= invn;
        out[0] = (float)(focal + 6.0 * cp + 5.0 * e);
#pragma unroll
        for (int a = 0; a < NACC; a++) g_acc[a] = 0.0;
    }
}

extern "C" void kernel_launch(void* const* d_in, const int* in_sizes, int n_in,
                              void* d_out, int out_size) {
    const float* p_hat   = (const float*)d_in[0];
    const float* u_hat   = (const float*)d_in[1];
    const int*   targets = (const int*)d_in[2];
    float* out = (float*)d_out;
    int n = in_sizes[0];

    fcl_main<<<GRID, BS>>>(p_hat, u_hat, targets, out, n);
}

// round 4
// speedup vs baseline: 1.0312x; 1.0143x over previous
#include <cuda_runtime.h>

#define NBINS 15
#define BS 256
#define NACC (2 + NBINS)
#define GRID 1036   // 148 SMs * 7 blocks (30.7KB smem/block -> 7 resident)

// [0]=focal sum, [1]=cp sum, [2..16]=per-bin sum of (y - p)
__device__ double g_acc[NACC];
__device__ unsigned g_count;   // zero-initialized at module load

__device__ __forceinline__ float warp_sum(float v) {
#pragma unroll
    for (int o = 16; o > 0; o >>= 1) v += __shfl_down_sync(0xffffffffu, v, o);
    return v;
}

__device__ __forceinline__ void process1(float p, float u, int t,
                                         float& facc, float& cacc,
                                         float* __restrict__ histcol) {
    bool pos = (t != 0);
    float tf = pos ? 1.0f : 0.0f;

    // focal: -alpha * (1-pt)^2 * log(pt + 1e-12), alpha = 2 - t
    float pt = pos ? p : 1.0f - p;
    float al = 2.0f - tf;
    float om = 1.0f - pt;
    float lg = __logf(pt + 1e-12f);
    facc = fmaf(-al * om * om, lg, facc);

    // confidence penalty: pos&p<tau -> u^2 ; !pos&p>tau -> (1-u)^2
    float v = pos ? u : 1.0f - u;
    bool cond = ((p < 0.7f) == pos);
    float m = v * v;
    if (cond) cacc += m;

    // ECE binning: bin = min((int)(p*15), 14)  (p >= 0)
    int b = (int)(p * 15.0f);
    b = b > NBINS - 1 ? NBINS - 1 : b;
    histcol[b * BS] += tf - p;
}

__global__ void __launch_bounds__(BS) fcl_main(
    const float* __restrict__ p_hat, const float* __restrict__ u_hat,
    const int* __restrict__ targets, float* __restrict__ out, int n)
{
    // Two independent per-thread histogram column sets -> two independent
    // LDS->FADD->STS chains (ptxas can prove histA/histB never alias).
    __shared__ float histA[NBINS * BS];
    __shared__ float histB[NBINS * BS];
    __shared__ float red[2][BS / 32];
    __shared__ bool is_last;

    const int tid  = threadIdx.x;
    const int lane = tid & 31;
    const int warp = tid >> 5;
    float* colA = &histA[tid];
    float* colB = &histB[tid];

#pragma unroll
    for (int b = 0; b < NBINS; b++) { histA[b * BS + tid] = 0.0f; histB[b * BS + tid] = 0.0f; }
    __syncthreads();

    float facc = 0.0f, cacc = 0.0f;

    const int n4 = n >> 2;
    const float4* __restrict__ p4 = (const float4*)p_hat;
    const float4* __restrict__ u4 = (const float4*)u_hat;
    const int4*   __restrict__ t4 = (const int4*)targets;

    const int stride = GRID * BS;
    int i = blockIdx.x * BS + tid;

    // unroll-by-2: 6 independent LDG.128 batched up front per iteration;
    // 8 elements split across the two histogram chains (4 + 4 deep).
    for (; i + stride < n4; i += 2 * stride) {
        float4 pv0 = __ldg(&p4[i]);
        float4 uv0 = __ldg(&u4[i]);
        int4   tv0 = __ldg(&t4[i]);
        float4 pv1 = __ldg(&p4[i + stride]);
        float4 uv1 = __ldg(&u4[i + stride]);
        int4   tv1 = __ldg(&t4[i + stride]);

        process1(pv0.x, uv0.x, tv0.x, facc, cacc, colA);
        process1(pv0.y, uv0.y, tv0.y, facc, cacc, colB);
        process1(pv0.z, uv0.z, tv0.z, facc, cacc, colA);
        process1(pv0.w, uv0.w, tv0.w, facc, cacc, colB);
        process1(pv1.x, uv1.x, tv1.x, facc, cacc, colA);
        process1(pv1.y, uv1.y, tv1.y, facc, cacc, colB);
        process1(pv1.z, uv1.z, tv1.z, facc, cacc, colA);
        process1(pv1.w, uv1.w, tv1.w, facc, cacc, colB);
    }
    for (; i < n4; i += stride) {
        float4 pv = __ldg(&p4[i]);
        float4 uv = __ldg(&u4[i]);
        int4   tv = __ldg(&t4[i]);
        process1(pv.x, uv.x, tv.x, facc, cacc, colA);
        process1(pv.y, uv.y, tv.y, facc, cacc, colB);
        process1(pv.z, uv.z, tv.z, facc, cacc, colA);
        process1(pv.w, uv.w, tv.w, facc, cacc, colB);
    }
    // scalar tail (n not divisible by 4)
    for (int j = (n4 << 2) + blockIdx.x * BS + tid; j < n; j += stride) {
        process1(p_hat[j], u_hat[j], targets[j], facc, cacc, colA);
    }
    __syncthreads();

    // block-reduce focal / cp
    facc = warp_sum(facc);
    cacc = warp_sum(cacc);
    if (lane == 0) { red[0][warp] = facc; red[1][warp] = cacc; }
    __syncthreads();
    if (warp == 0) {
        float f = (lane < BS / 32) ? red[0][lane] : 0.0f;
        float c = (lane < BS / 32) ? red[1][lane] : 0.0f;
        f = warp_sum(f);
        c = warp_sum(c);
        if (lane == 0) {
            atomicAdd(&g_acc[0], (double)f);
            atomicAdd(&g_acc[1], (double)c);
        }
    }

    // block-reduce each bin column (A+B), one double atomic per bin per block
    for (int b = warp; b < NBINS; b += BS / 32) {
        float s = 0.0f;
#pragma unroll
        for (int j = lane; j < BS; j += 32) s += histA[b * BS + j] + histB[b * BS + j];
        s = warp_sum(s);
        if (lane == 0) atomicAdd(&g_acc[2 + b], (double)s);
    }

    // last-block-done: finalize + reset accumulators for next graph replay
    __threadfence();
    if (tid == 0) {
        unsigned v = atomicInc(&g_count, GRID - 1);  // wraps to 0 on last block
        is_last = (v == GRID - 1);
    }
    __syncthreads();
    if (is_last && tid == 0) {
        double invn  = 1.0 / (double)n;
        double focal = g_acc[0] * invn;
        double cp    = g_acc[1] * invn;
        double e     = 0.0;
#pragma unroll
        for (int b = 0; b < NBINS; b++) e += fabs(g_acc[2 + b]);
        e *= invn;
        out[0] = (float)(focal + 6.0 * cp + 5.0 * e);
#pragma unroll
        for (int a = 0; a < NACC; a++) g_acc[a] = 0.0;
    }
}

extern "C" void kernel_launch(void* const* d_in, const int* in_sizes, int n_in,
                              void* d_out, int out_size) {
    const float* p_hat   = (const float*)d_in[0];
    const float* u_hat   = (const float*)d_in[1];
    const int*   targets = (const int*)d_in[2];
    float* out = (float*)d_out;
    int n = in_sizes[0];

    fcl_main<<<GRID, BS>>>(p_hat, u_hat, targets, out, n);
}

// round 5
// speedup vs baseline: 1.1131x; 1.0794x over previous
#include <cuda_runtime.h>

#define NBINS 15
#define BS 256
#define NACC (2 + NBINS)
#define GRID 888   // 148 SMs * 6 blocks (reg-limited at 6 via launch_bounds)

// [0]=focal sum, [1]=cp sum, [2..16]=per-bin sum of (y - p)
__device__ double g_acc[NACC];
__device__ unsigned g_count;   // zero-initialized at module load

__device__ __forceinline__ float warp_sum(float v) {
#pragma unroll
    for (int o = 16; o > 0; o >>= 1) v += __shfl_down_sync(0xffffffffu, v, o);
    return v;
}

__device__ __forceinline__ void process1(float p, float u, int t,
                                         float& facc, float& cacc,
                                         float* __restrict__ histcol) {
    bool pos = (t != 0);
    float tf = pos ? 1.0f : 0.0f;

    // focal: -alpha * (1-pt)^2 * log(pt + 1e-12), alpha = 2 - t
    float pt = pos ? p : 1.0f - p;
    float al = 2.0f - tf;
    float om = 1.0f - pt;
    float lg = __logf(pt + 1e-12f);
    facc = fmaf(-al * om * om, lg, facc);

    // confidence penalty: pos&p<tau -> u^2 ; !pos&p>tau -> (1-u)^2
    float v = pos ? u : 1.0f - u;
    bool cond = ((p < 0.7f) == pos);
    float m = v * v;
    if (cond) cacc += m;

    // ECE binning: bin = min((int)(p*15), 14)  (p >= 0)
    int b = (int)(p * 15.0f);
    b = b > NBINS - 1 ? NBINS - 1 : b;
    histcol[b * BS] += tf - p;
}

__device__ __forceinline__ void process4(float4 pv, float4 uv, int4 tv,
                                         float& facc, float& cacc,
                                         float* __restrict__ colA,
                                         float* __restrict__ colB) {
    process1(pv.x, uv.x, tv.x, facc, cacc, colA);
    process1(pv.y, uv.y, tv.y, facc, cacc, colB);
    process1(pv.z, uv.z, tv.z, facc, cacc, colA);
    process1(pv.w, uv.w, tv.w, facc, cacc, colB);
}

__global__ void __launch_bounds__(BS, 6) fcl_main(
    const float* __restrict__ p_hat, const float* __restrict__ u_hat,
    const int* __restrict__ targets, float* __restrict__ out, int n)
{
    // Two independent per-thread histogram column sets -> two independent
    // LDS->FADD->STS chains.
    __shared__ float histA[NBINS * BS];
    __shared__ float histB[NBINS * BS];
    __shared__ float red[2][BS / 32];
    __shared__ bool is_last;

    const int tid  = threadIdx.x;
    const int lane = tid & 31;
    const int warp = tid >> 5;
    float* colA = &histA[tid];
    float* colB = &histB[tid];

#pragma unroll
    for (int b = 0; b < NBINS; b++) { histA[b * BS + tid] = 0.0f; histB[b * BS + tid] = 0.0f; }
    __syncthreads();

    float facc = 0.0f, cacc = 0.0f;

    const int n4 = n >> 2;
    const float4* __restrict__ p4 = (const float4*)p_hat;
    const float4* __restrict__ u4 = (const float4*)u_hat;
    const int4*   __restrict__ t4 = (const int4*)targets;

    const int stride = GRID * BS;
    const int i0 = blockIdx.x * BS + tid;

    // Software-pipelined grid-stride loop: iteration t+1's loads are issued
    // BEFORE iteration t's compute, so DRAM requests are in flight while the
    // SM is busy (breaks the load->consume->load lockstep burst pattern).
    if (i0 < n4) {
        int iters = (n4 - i0 + stride - 1) / stride;  // >= 1
        float4 pv = __ldg(&p4[i0]);
        float4 uv = __ldg(&u4[i0]);
        int4   tv = __ldg(&t4[i0]);
        int i = i0 + stride;
        for (int it = 1; it < iters; it++, i += stride) {
            float4 pn = __ldg(&p4[i]);      // prefetch next tile (unconditional)
            float4 un = __ldg(&u4[i]);
            int4   tn = __ldg(&t4[i]);
            process4(pv, uv, tv, facc, cacc, colA, colB);
            pv = pn; uv = un; tv = tn;
        }
        process4(pv, uv, tv, facc, cacc, colA, colB);  // epilogue
    }
    // scalar tail (n not divisible by 4)
    for (int j = (n4 << 2) + i0; j < n; j += stride) {
        process1(p_hat[j], u_hat[j], targets[j], facc, cacc, colA);
    }
    __syncthreads();

    // block-reduce focal / cp
    facc = warp_sum(facc);
    cacc = warp_sum(cacc);
    if (lane == 0) { red[0][warp] = facc; red[1][warp] = cacc; }
    __syncthreads();
    if (warp == 0) {
        float f = (lane < BS / 32) ? red[0][lane] : 0.0f;
        float c = (lane < BS / 32) ? red[1][lane] : 0.0f;
        f = warp_sum(f);
        c = warp_sum(c);
        if (lane == 0) {
            atomicAdd(&g_acc[0], (double)f);
            atomicAdd(&g_acc[1], (double)c);
        }
    }

    // block-reduce each bin column (A+B), one double atomic per bin per block
    for (int b = warp; b < NBINS; b += BS / 32) {
        float s = 0.0f;
#pragma unroll
        for (int j = lane; j < BS; j += 32) s += histA[b * BS + j] + histB[b * BS + j];
        s = warp_sum(s);
        if (lane == 0) atomicAdd(&g_acc[2 + b], (double)s);
    }

    // last-block-done: finalize + reset accumulators for next graph replay
    __threadfence();
    if (tid == 0) {
        unsigned v = atomicInc(&g_count, GRID - 1);  // wraps to 0 on last block
        is_last = (v == GRID - 1);
    }
    __syncthreads();
    if (is_last && tid == 0) {
        double invn  = 1.0 / (double)n;
        double focal = g_acc[0] * invn;
        double cp    = g_acc[1] * invn;
        double e     = 0.0;
#pragma unroll
        for (int b = 0; b < NBINS; b++) e += fabs(g_acc[2 + b]);
        e *= invn;
        out[0] = (float)(focal + 6.0 * cp + 5.0 * e);
#pragma unroll
        for (int a = 0; a < NACC; a++) g_acc[a] = 0.0;
    }
}

extern "C" void kernel_launch(void* const* d_in, const int* in_sizes, int n_in,
                              void* d_out, int out_size) {
    const float* p_hat   = (const float*)d_in[0];
    const float* u_hat   = (const float*)d_in[1];
    const int*   targets = (const int*)d_in[2];
    float* out = (float*)d_out;
    int n = in_sizes[0];

    fcl_main<<<GRID, BS>>>(p_hat, u_hat, targets, out, n);
}

// round 6
// speedup vs baseline: 1.1882x; 1.0675x over previous
#include <cuda_runtime.h>

#define NBINS 15
#define BS 256
#define NACC (2 + NBINS)
#define GRID 592   // 148 SMs * 4 blocks (reg-budgeted for 2-stage pipeline)

// [0]=focal sum, [1]=cp sum, [2..16]=per-bin sum of (y - p)
__device__ double g_acc[NACC];
__device__ unsigned g_count;   // zero-initialized at module load

__device__ __forceinline__ float warp_sum(float v) {
#pragma unroll
    for (int o = 16; o > 0; o >>= 1) v += __shfl_down_sync(0xffffffffu, v, o);
    return v;
}

__device__ __forceinline__ void process1(float p, float u, int t,
                                         float& facc, float& cacc,
                                         float* __restrict__ histcol) {
    bool pos = (t != 0);
    float tf = pos ? 1.0f : 0.0f;

    // focal: -alpha * (1-pt)^2 * log(pt + 1e-12), alpha = 2 - t
    float pt = pos ? p : 1.0f - p;
    float om = 1.0f - pt;
    float om2 = om * om;
    if (!pos) om2 += om2;               // alpha fold: x2 for negatives
    float lg = __logf(pt + 1e-12f);
    facc = fmaf(-om2, lg, facc);

    // confidence penalty: pos&p<tau -> u^2 ; !pos&p>tau -> (1-u)^2
    float v = pos ? u : 1.0f - u;
    bool cond = ((p < 0.7f) == pos);
    float m = v * v;
    if (cond) cacc += m;

    // ECE binning: bin = min((int)(p*15), 14)  (p >= 0)
    int b = (int)fminf(p * 15.0f, 14.0f);
    histcol[b * BS] += tf - p;
}

__device__ __forceinline__ void process4(float4 pv, float4 uv, int4 tv,
                                         float& facc, float& cacc,
                                         float* __restrict__ colA,
                                         float* __restrict__ colB) {
    process1(pv.x, uv.x, tv.x, facc, cacc, colA);
    process1(pv.y, uv.y, tv.y, facc, cacc, colB);
    process1(pv.z, uv.z, tv.z, facc, cacc, colA);
    process1(pv.w, uv.w, tv.w, facc, cacc, colB);
}

__global__ void __launch_bounds__(BS, 4) fcl_main(
    const float* __restrict__ p_hat, const float* __restrict__ u_hat,
    const int* __restrict__ targets, float* __restrict__ out, int n)
{
    __shared__ float histA[NBINS * BS];
    __shared__ float histB[NBINS * BS];
    __shared__ float red[2][BS / 32];
    __shared__ bool is_last;

    const int tid  = threadIdx.x;
    const int lane = tid & 31;
    const int warp = tid >> 5;
    float* colA = &histA[tid];
    float* colB = &histB[tid];

#pragma unroll
    for (int b = 0; b < NBINS; b++) { histA[b * BS + tid] = 0.0f; histB[b * BS + tid] = 0.0f; }
    __syncthreads();

    float facc = 0.0f, cacc = 0.0f;

    const int n4 = n >> 2;
    const float4* __restrict__ p4 = (const float4*)p_hat;
    const float4* __restrict__ u4 = (const float4*)u_hat;
    const int4*   __restrict__ t4 = (const int4*)targets;

    const int stride = GRID * BS;
    const int i0 = blockIdx.x * BS + tid;

    // 2-deep software pipeline over 2-tile rounds: tiles A (@it) and B (@it+1)
    // are resident while tiles @it+2, @it+3 stream in => 6 LDG.128 in flight
    // per warp throughout the steady state.
    if (i0 < n4) {
        const int iters = (n4 - i0 + stride - 1) / stride;   // >= 1
        float4 pA, uA, pB, uB; int4 tA, tB;
        pA = __ldg(&p4[i0]); uA = __ldg(&u4[i0]); tA = __ldg(&t4[i0]);
        if (iters >= 2) {
            pB = __ldg(&p4[i0 + stride]); uB = __ldg(&u4[i0 + stride]); tB = __ldg(&t4[i0 + stride]);
        }
        int it = 0;
        int i2 = i0 + 2 * stride;
        for (; it + 3 < iters; it += 2, i2 += 2 * stride) {
            float4 pn = __ldg(&p4[i2]);
            float4 un = __ldg(&u4[i2]);
            int4   tn = __ldg(&t4[i2]);
            float4 pm = __ldg(&p4[i2 + stride]);
            float4 um = __ldg(&u4[i2 + stride]);
            int4   tm = __ldg(&t4[i2 + stride]);
            process4(pA, uA, tA, facc, cacc, colA, colB);
            process4(pB, uB, tB, facc, cacc, colB, colA);
            pA = pn; uA = un; tA = tn;
            pB = pm; uB = um; tB = tm;
        }
        // epilogue: rem in {1,2,3}
        int rem = iters - it;
        process4(pA, uA, tA, facc, cacc, colA, colB);
        if (rem >= 2) process4(pB, uB, tB, facc, cacc, colB, colA);
        if (rem >= 3) {
            float4 pc = __ldg(&p4[i2]);
            float4 uc = __ldg(&u4[i2]);
            int4   tc = __ldg(&t4[i2]);
            process4(pc, uc, tc, facc, cacc, colA, colB);
        }
    }
    // scalar tail (n not divisible by 4)
    for (int j = (n4 << 2) + i0; j < n; j += stride) {
        process1(p_hat[j], u_hat[j], targets[j], facc, cacc, colA);
    }
    __syncthreads();

    // block-reduce focal / cp
    facc = warp_sum(facc);
    cacc = warp_sum(cacc);
    if (lane == 0) { red[0][warp] = facc; red[1][warp] = cacc; }
    __syncthreads();
    if (warp == 0) {
        float f = (lane < BS / 32) ? red[0][lane] : 0.0f;
        float c = (lane < BS / 32) ? red[1][lane] : 0.0f;
        f = warp_sum(f);
        c = warp_sum(c);
        if (lane == 0) {
            atomicAdd(&g_acc[0], (double)f);
            atomicAdd(&g_acc[1], (double)c);
        }
    }

    // block-reduce each bin column (A+B), one double atomic per bin per block
    for (int b = warp; b < NBINS; b += BS / 32) {
        float s = 0.0f;
#pragma unroll
        for (int j = lane; j < BS; j += 32) s += histA[b * BS + j] + histB[b * BS + j];
        s = warp_sum(s);
        if (lane == 0) atomicAdd(&g_acc[2 + b], (double)s);
    }

    // last-block-done: finalize + reset accumulators for next graph replay
    __threadfence();
    if (tid == 0) {
        unsigned v = atomicInc(&g_count, GRID - 1);  // wraps to 0 on last block
        is_last = (v == GRID - 1);
    }
    __syncthreads();
    if (is_last && tid == 0) {
        double invn  = 1.0 / (double)n;
        double focal = g_acc[0] * invn;
        double cp    = g_acc[1] * invn;
        double e     = 0.0;
#pragma unroll
        for (int b = 0; b < NBINS; b++) e += fabs(g_acc[2 + b]);
        e *= invn;
        out[0] = (float)(focal + 6.0 * cp + 5.0 * e);
#pragma unroll
        for (int a = 0; a < NACC; a++) g_acc[a] = 0.0;
    }
}

extern "C" void kernel_launch(void* const* d_in, const int* in_sizes, int n_in,
                              void* d_out, int out_size) {
    const float* p_hat   = (const float*)d_in[0];
    const float* u_hat   = (const float*)d_in[1];
    const int*   targets = (const int*)d_in[2];
    float* out = (float*)d_out;
    int n = in_sizes[0];

    fcl_main<<<GRID, BS>>>(p_hat, u_hat, targets, out, n);
}

// round 7
// speedup vs baseline: 1.1890x; 1.0008x over previous
#include <cuda_runtime.h>

#define NBINS 15
#define BS 256
#define NACC (2 + NBINS)
#define GRID 592   // 148 SMs * 4 blocks

// [0]=focal sum, [1]=cp sum, [2..16]=per-bin sum of (y - p)
__device__ double g_acc[NACC];
__device__ unsigned g_count;   // zero-initialized at module load

__device__ __forceinline__ float warp_sum(float v) {
#pragma unroll
    for (int o = 16; o > 0; o >>= 1) v += __shfl_down_sync(0xffffffffu, v, o);
    return v;
}

__device__ __forceinline__ unsigned long long mkpolicy(float frac) {
    unsigned long long pol;
    asm("createpolicy.fractional.L2::evict_last.b64 %0, %1;"
        : "=l"(pol) : "f"(frac));
    return pol;
}

// Pinned (evict_last) vector load: hashed 75% of p/u lines stay L2-resident
// across graph replays, cutting steady-state DRAM traffic.
__device__ __forceinline__ float4 ldg_pin_f4(const float4* p, unsigned long long pol) {
    float4 v;
    asm volatile("ld.global.nc.L2::cache_hint.v4.f32 {%0,%1,%2,%3}, [%4], %5;"
                 : "=f"(v.x), "=f"(v.y), "=f"(v.z), "=f"(v.w)
                 : "l"(p), "l"(pol));
    return v;
}

__device__ __forceinline__ void process1(float p, float u, int t,
                                         float& facc, float& cacc,
                                         float* __restrict__ histcol) {
    bool pos = (t != 0);
    float tf = pos ? 1.0f : 0.0f;

    // focal: -alpha * (1-pt)^2 * log(pt + 1e-12), alpha = 2 - t
    float pt = pos ? p : 1.0f - p;
    float om = 1.0f - pt;
    float om2 = om * om;
    if (!pos) om2 += om2;               // alpha fold: x2 for negatives
    float lg = __logf(pt + 1e-12f);
    facc = fmaf(-om2, lg, facc);

    // confidence penalty: pos&p<tau -> u^2 ; !pos&p>tau -> (1-u)^2
    float v = pos ? u : 1.0f - u;
    bool cond = ((p < 0.7f) == pos);
    float m = v * v;
    if (cond) cacc += m;

    // ECE binning: bin = min((int)(p*15), 14)  (p >= 0)
    int b = (int)fminf(p * 15.0f, 14.0f);
    histcol[b * BS] += tf - p;
}

__device__ __forceinline__ void process4(float4 pv, float4 uv, int4 tv,
                                         float& facc, float& cacc,
                                         float* __restrict__ colA,
                                         float* __restrict__ colB) {
    process1(pv.x, uv.x, tv.x, facc, cacc, colA);
    process1(pv.y, uv.y, tv.y, facc, cacc, colB);
    process1(pv.z, uv.z, tv.z, facc, cacc, colA);
    process1(pv.w, uv.w, tv.w, facc, cacc, colB);
}

__global__ void __launch_bounds__(BS, 4) fcl_main(
    const float* __restrict__ p_hat, const float* __restrict__ u_hat,
    const int* __restrict__ targets, float* __restrict__ out, int n)
{
    __shared__ float histA[NBINS * BS];
    __shared__ float histB[NBINS * BS];
    __shared__ float red[2][BS / 32];
    __shared__ bool is_last;

    const int tid  = threadIdx.x;
    const int lane = tid & 31;
    const int warp = tid >> 5;
    float* colA = &histA[tid];
    float* colB = &histB[tid];

#pragma unroll
    for (int b = 0; b < NBINS; b++) { histA[b * BS + tid] = 0.0f; histB[b * BS + tid] = 0.0f; }
    __syncthreads();

    const unsigned long long pol = mkpolicy(0.75f);  // pin ~100MB of p+u in L2

    float facc = 0.0f, cacc = 0.0f;

    const int n4 = n >> 2;
    const float4* __restrict__ p4 = (const float4*)p_hat;
    const float4* __restrict__ u4 = (const float4*)u_hat;
    const int4*   __restrict__ t4 = (const int4*)targets;

    const int stride = GRID * BS;
    const int i0 = blockIdx.x * BS + tid;

    // 2-deep software pipeline over 2-tile rounds => 6 LDG.128 in flight/warp.
    if (i0 < n4) {
        const int iters = (n4 - i0 + stride - 1) / stride;   // >= 1
        float4 pA, uA, pB, uB; int4 tA, tB;
        pA = ldg_pin_f4(&p4[i0], pol); uA = ldg_pin_f4(&u4[i0], pol); tA = __ldg(&t4[i0]);
        if (iters >= 2) {
            pB = ldg_pin_f4(&p4[i0 + stride], pol);
            uB = ldg_pin_f4(&u4[i0 + stride], pol);
            tB = __ldg(&t4[i0 + stride]);
        }
        int it = 0;
        int i2 = i0 + 2 * stride;
        for (; it + 3 < iters; it += 2, i2 += 2 * stride) {
            float4 pn = ldg_pin_f4(&p4[i2], pol);
            float4 un = ldg_pin_f4(&u4[i2], pol);
            int4   tn = __ldg(&t4[i2]);
            float4 pm = ldg_pin_f4(&p4[i2 + stride], pol);
            float4 um = ldg_pin_f4(&u4[i2 + stride], pol);
            int4   tm = __ldg(&t4[i2 + stride]);
            process4(pA, uA, tA, facc, cacc, colA, colB);
            process4(pB, uB, tB, facc, cacc, colB, colA);
            pA = pn; uA = un; tA = tn;
            pB = pm; uB = um; tB = tm;
        }
        // epilogue: rem in {1,2,3}
        int rem = iters - it;
        process4(pA, uA, tA, facc, cacc, colA, colB);
        if (rem >= 2) process4(pB, uB, tB, facc, cacc, colB, colA);
        if (rem >= 3) {
            float4 pc = ldg_pin_f4(&p4[i2], pol);
            float4 uc = ldg_pin_f4(&u4[i2], pol);
            int4   tc = __ldg(&t4[i2]);
            process4(pc, uc, tc, facc, cacc, colA, colB);
        }
    }
    // scalar tail (n not divisible by 4)
    for (int j = (n4 << 2) + i0; j < n; j += stride) {
        process1(p_hat[j], u_hat[j], targets[j], facc, cacc, colA);
    }
    __syncthreads();

    // block-reduce focal / cp
    facc = warp_sum(facc);
    cacc = warp_sum(cacc);
    if (lane == 0) { red[0][warp] = facc; red[1][warp] = cacc; }
    __syncthreads();
    if (warp == 0) {
        float f = (lane < BS / 32) ? red[0][lane] : 0.0f;
        float c = (lane < BS / 32) ? red[1][lane] : 0.0f;
        f = warp_sum(f);
        c = warp_sum(c);
        if (lane == 0) {
            atomicAdd(&g_acc[0], (double)f);
            atomicAdd(&g_acc[1], (double)c);
        }
    }

    // block-reduce each bin column (A+B), one double atomic per bin per block
    for (int b = warp; b < NBINS; b += BS / 32) {
        float s = 0.0f;
#pragma unroll
        for (int j = lane; j < BS; j += 32) s += histA[b * BS + j] + histB[b * BS + j];
        s = warp_sum(s);
        if (lane == 0) atomicAdd(&g_acc[2 + b], (double)s);
    }

    // last-block-done: finalize + reset accumulators for next graph replay
    __threadfence();
    if (tid == 0) {
        unsigned v = atomicInc(&g_count, GRID - 1);  // wraps to 0 on last block
        is_last = (v == GRID - 1);
    }
    __syncthreads();
    if (is_last && tid == 0) {
        double invn  = 1.0 / (double)n;
        double focal = g_acc[0] * invn;
        double cp    = g_acc[1] * invn;
        double e     = 0.0;
#pragma unroll
        for (int b = 0; b < NBINS; b++) e += fabs(g_acc[2 + b]);
        e *= invn;
        out[0] = (float)(focal + 6.0 * cp + 5.0 * e);
#pragma unroll
        for (int a = 0; a < NACC; a++) g_acc[a] = 0.0;
    }
}

extern "C" void kernel_launch(void* const* d_in, const int* in_sizes, int n_in,
                              void* d_out, int out_size) {
    const float* p_hat   = (const float*)d_in[0];
    const float* u_hat   = (const float*)d_in[1];
    const int*   targets = (const int*)d_in[2];
    float* out = (float*)d_out;
    int n = in_sizes[0];

    fcl_main<<<GRID, BS>>>(p_hat, u_hat, targets, out, n);
}